// round 8
// baseline (speedup 1.0000x reference)
#include <cuda_runtime.h>
#include <math.h>

#define H     2048
#define NH    16
#define NKV   4
#define HD    128
#define G     4
#define B     32
#define S     4096
#define QKV_N 3072          // (NH + 2*NKV) * HD
#define KSPLIT 16
#define KCHUNK 128          // H / KSPLIT
#define JTILE  128
#define CHUNK  256
#define NCHUNK 16           // S / CHUNK
#define TS     16           // s-rows per smem tile
// q pre-scale: HD^-0.5 * log2(e)  (softmax via exp2)
#define ATT_SCALE2 0.12753425936722887f

typedef unsigned long long ull;

// ---------------- scratch (device globals; no allocation) ----------------
__device__ float g_partA[KSPLIT * B * QKV_N];          // qkv GEMV partials
__device__ float g_qkv[B * QKV_N];                     // qkv = hidden@Wqkv + b
__device__ float g_part_acc[B * NKV * NCHUNK * G * HD];// flash-decode partial pv sums
__device__ float g_part_l[B * NKV * NCHUNK * G];       // partial exp sums
__device__ float g_att[B * NH * HD];                   // attention output (pre-Wo)
__device__ float g_partE[KSPLIT * B * H];              // out GEMV partials

#define ACC_N4 (B * NKV * NCHUNK * G * HD / 4)         // 262144 float4

// ---------------- packed f32x2 helpers ----------------
__device__ __forceinline__ ull pk2(float x, float y) {
    ull r;
    asm("mov.b64 %0, {%1, %2};" : "=l"(r) : "f"(x), "f"(y));
    return r;
}
__device__ __forceinline__ ull f2fma(ull a, ull b, ull c) {
    ull d;
    asm("fma.rn.f32x2 %0, %1, %2, %3;" : "=l"(d) : "l"(a), "l"(b), "l"(c));
    return d;
}
__device__ __forceinline__ ull f2mul(ull a, ull b) {
    ull d;
    asm("mul.rn.f32x2 %0, %1, %2;" : "=l"(d) : "l"(a), "l"(b));
    return d;
}
__device__ __forceinline__ void upk2(ull v, float& lo, float& hi) {
    asm("mov.b64 {%0, %1}, %2;" : "=f"(lo), "=f"(hi) : "l"(v));
}

// ---------------- zero partials: 3 launches so gemm_qkv lands at graph idx 3 --
__global__ void __launch_bounds__(256) zeroA() {
    int i = blockIdx.x * 256 + threadIdx.x;
    if (i < ACC_N4 / 2) ((float4*)g_part_acc)[i] = make_float4(0.f, 0.f, 0.f, 0.f);
}
__global__ void __launch_bounds__(256) zeroB() {
    int i = blockIdx.x * 256 + threadIdx.x;
    if (i < ACC_N4 / 2) ((float4*)g_part_acc)[ACC_N4 / 2 + i] = make_float4(0.f, 0.f, 0.f, 0.f);
}
__global__ void __launch_bounds__(256) zeroC() {
    int i = blockIdx.x * 256 + threadIdx.x;
    if (i < B * NKV * NCHUNK * G / 4)
        ((float4*)g_part_l)[i] = make_float4(0.f, 0.f, 0.f, 0.f);
}

// ---------------- GEMV body: P[ks][32][N] partials of X[32][2048] @ W[2048][N] ----------------
// 256 threads = 64 j-pairs x 4 b-octets. Per thread: 2 output columns x 8 batch
// rows. Per k: 1 LDG.64 (two W cols) + 2 LDS.128 (8 x-values, broadcast) +
// 2 packs + 8 FFMA2 = 16 MACs in ~14 slots, no duplicated W stream.
__device__ __forceinline__ void gemm_body(const float* __restrict__ X,
                                          const float* __restrict__ W,
                                          float* __restrict__ P, int N) {
    __shared__ __align__(16) float xs[KCHUNK * 36];   // [k][b] padded rows
    const int tid = threadIdx.x;
    const int j2 = tid & 63;           // j-pair index
    const int bq = tid >> 6;           // batch octet 0..3
    const int j = blockIdx.x * JTILE + j2 * 2;
    const int ks = blockIdx.y;
    const int kbase = ks * KCHUNK;

    for (int idx = tid; idx < KCHUNK * 32; idx += 256) {
        int b = idx >> 7;              // 0..31
        int k = idx & 127;             // coalesced per b-row
        xs[k * 36 + b] = X[b * H + kbase + k];
    }
    __syncthreads();

    ull acc[8];
#pragma unroll
    for (int p = 0; p < 8; p++) acc[p] = 0ull;

    const float2* Wp = (const float2*)(W + (size_t)kbase * N + j);
    const int strideW = N / 2;
#pragma unroll 8
    for (int k = 0; k < KCHUNK; k++) {
        float2 w = Wp[(size_t)k * strideW];
        ull w0 = pk2(w.x, w.x);
        ull w1 = pk2(w.y, w.y);
        const ulonglong2* hp =
            reinterpret_cast<const ulonglong2*>(xs + k * 36 + bq * 8);
        ulonglong2 xa = hp[0], xb = hp[1];
        acc[0] = f2fma(xa.x, w0, acc[0]);
        acc[1] = f2fma(xa.y, w0, acc[1]);
        acc[2] = f2fma(xb.x, w0, acc[2]);
        acc[3] = f2fma(xb.y, w0, acc[3]);
        acc[4] = f2fma(xa.x, w1, acc[4]);
        acc[5] = f2fma(xa.y, w1, acc[5]);
        acc[6] = f2fma(xb.x, w1, acc[6]);
        acc[7] = f2fma(xb.y, w1, acc[7]);
    }

    // acc[p]   : column j,   batch rows bq*8 + {2p, 2p+1}
    // acc[4+p] : column j+1, same rows
    float* Pp = P + (size_t)ks * 32 * N + (size_t)(bq * 8) * N + j;
#pragma unroll
    for (int p = 0; p < 4; p++) {
        float lo, hi;
        upk2(acc[p], lo, hi);
        Pp[(size_t)(2 * p) * N]     = lo;
        Pp[(size_t)(2 * p + 1) * N] = hi;
        upk2(acc[4 + p], lo, hi);
        Pp[(size_t)(2 * p) * N + 1]     = lo;
        Pp[(size_t)(2 * p + 1) * N + 1] = hi;
    }
}

__global__ void __launch_bounds__(256) gemm_qkv(const float* __restrict__ hidden,
                                                const float* __restrict__ Wqkv) {
    gemm_body(hidden, Wqkv, g_partA, QKV_N);
}
__global__ void __launch_bounds__(256) gemm_out(const float* __restrict__ Wo) {
    gemm_body(g_att, Wo, g_partE, H);
}

// ---------------- partial reduction (+ optional bias), float4-vectorized ------
__device__ __forceinline__ void reduce_body(const float* __restrict__ P,
                                            const float* __restrict__ bias,
                                            float* __restrict__ out, int N) {
    const int n4 = 32 * N / 4;
    int i = blockIdx.x * 256 + threadIdx.x;
    if (i >= n4) return;
    float4 v[KSPLIT];
#pragma unroll
    for (int ks = 0; ks < KSPLIT; ks++)
        v[ks] = ((const float4*)P)[ks * n4 + i];
    float4 s = make_float4(0.f, 0.f, 0.f, 0.f);
#pragma unroll
    for (int ks = 0; ks < KSPLIT; ks++) {
        s.x += v[ks].x; s.y += v[ks].y; s.z += v[ks].z; s.w += v[ks].w;
    }
    if (bias) {
        float4 bv = ((const float4*)bias)[i % (N / 4)];
        s.x += bv.x; s.y += bv.y; s.z += bv.z; s.w += bv.w;
    }
    ((float4*)out)[i] = s;
}
__global__ void __launch_bounds__(256) reduce_qkv(const float* __restrict__ bqkv) {
    reduce_body(g_partA, bqkv, g_qkv, QKV_N);
}
__global__ void __launch_bounds__(256) reduce_out(float* __restrict__ out) {
    reduce_body(g_partE, nullptr, out, H);
}

// ---------------- cp.async helpers ----------------
__device__ __forceinline__ void cp16(float* dst_smem, const float* src_gmem) {
    unsigned sa = (unsigned)__cvta_generic_to_shared(dst_smem);
    asm volatile("cp.async.cg.shared.global [%0], [%1], 16;"
                 :: "r"(sa), "l"(src_gmem) : "memory");
}
__device__ __forceinline__ void cp_commit() {
    asm volatile("cp.async.commit_group;" ::: "memory");
}
__device__ __forceinline__ void cp_wait2() {
    asm volatile("cp.async.wait_group 2;" ::: "memory");
}

// ---------------- flash-decode attention chunk (smem 3-stage pipeline) --------
// grid: (NCHUNK, NKV, B), block 256 (8 warps), 4 blocks/SM pinned (regs<=64).
// Loader exploits idx structure: thread's 4 cp.asyncs are K/V rows {r0, r0+8}
// at the i-invariant 16-B chunk ck -> ~6 registers of loader state.
__global__ void __launch_bounds__(256, 4) attn_chunk(const float* __restrict__ cache,
                                                     const int* __restrict__ seq_lens) {
    __shared__ __align__(16) float sk[3][TS * 128];   // 24 KB
    __shared__ __align__(16) float sv[3][TS * 128];   // 24 KB

    const int c = blockIdx.x, kvh = blockIdx.y, b = blockIdx.z;
    const int seq = seq_lens[b];
    const int sbeg = c * CHUNK;
    if (sbeg >= seq) return;                    // partials pre-zeroed
    const int tid = threadIdx.x;
    const size_t obase = (size_t)(b * NKV + kvh) * NCHUNK + c;

    const int send = min(sbeg + CHUNK, seq);
    const int last = seq - 1;
    const int ntiles = (send - sbeg + TS - 1) / TS;

    const int lane = tid & 31, wid = tid >> 5;
    const int h = lane & 3;
    const int dgrp = lane >> 2;

    const float* kcache = cache + (size_t)b * S * 1024 + kvh * HD;
    const float* knew = g_qkv + b * QKV_N + NH * HD + kvh * HD;
    const float* vnew = g_qkv + b * QKV_N + (NH + NKV) * HD + kvh * HD;

    // lean loader state
    const int ck4 = (tid & 31) * 4;        // float offset of this thread's 16-B chunk
    const int r0  = tid >> 5;              // rows r0 and r0+8
    const int dst0 = r0 * 128 + ck4;
    const float* kc_r = kcache + (size_t)r0 * 1024 + ck4;   // K row r0, this chunk
    const float* knew_ck = knew + ck4;
    const float* vnew_ck = vnew + ck4;

    auto load_tile = [&](int stage, int ts0) {
        const float* basep = kc_r + (size_t)ts0 * 1024;
        const int s0 = ts0 + r0, s1 = s0 + 8;
        if (s0 < send) {
            cp16(sk[stage] + dst0, (s0 == last) ? knew_ck : basep);
            cp16(sv[stage] + dst0, (s0 == last) ? vnew_ck : basep + 512);
        }
        if (s1 < send) {
            cp16(sk[stage] + dst0 + 1024, (s1 == last) ? knew_ck : basep + 8192);
            cp16(sv[stage] + dst0 + 1024, (s1 == last) ? vnew_ck : basep + 8704);
        }
    };

    const ulonglong2* qp2 =
        (const ulonglong2*)(g_qkv + b * QKV_N + (kvh * G + h) * HD);
    const ull s2 = pk2(ATT_SCALE2, ATT_SCALE2);
    ull q2[8];
    {
        ulonglong2 qa = qp2[dgrp], qb = qp2[8 + dgrp],
                   qc = qp2[16 + dgrp], qd = qp2[24 + dgrp];
        q2[0] = f2mul(qa.x, s2); q2[1] = f2mul(qa.y, s2);
        q2[2] = f2mul(qb.x, s2); q2[3] = f2mul(qb.y, s2);
        q2[4] = f2mul(qc.x, s2); q2[5] = f2mul(qc.y, s2);
        q2[6] = f2mul(qd.x, s2); q2[7] = f2mul(qd.y, s2);
    }

    load_tile(0, sbeg);
    cp_commit();
    if (ntiles > 1) load_tile(1, sbeg + TS);
    cp_commit();
    if (ntiles > 2) load_tile(2, sbeg + 2 * TS);
    cp_commit();

    ull acc2[8];
#pragma unroll
    for (int i = 0; i < 8; i++) acc2[i] = 0ull;
    float lsum = 0.f;

    int cst = 0;   // stage being consumed
    for (int t = 0; t < ntiles; t++) {
        cp_wait2();
        __syncthreads();
        const ulonglong2* kt = (const ulonglong2*)sk[cst];
        const ulonglong2* vt = (const ulonglong2*)sv[cst];
        const int ts0 = sbeg + t * TS;
#pragma unroll
        for (int rr = 0; rr < 2; rr++) {
            const int row = wid * 2 + rr;
            if (ts0 + row < send) {
                const ulonglong2* kr = kt + row * 32;
                const ulonglong2* vr = vt + row * 32;
                ulonglong2 kA = kr[dgrp], kB = kr[8 + dgrp],
                           kC = kr[16 + dgrp], kD = kr[24 + dgrp];
                ull d2 = f2mul(kA.x, q2[0]);
                d2 = f2fma(kA.y, q2[1], d2);
                d2 = f2fma(kB.x, q2[2], d2);
                d2 = f2fma(kB.y, q2[3], d2);
                d2 = f2fma(kC.x, q2[4], d2);
                d2 = f2fma(kC.y, q2[5], d2);
                d2 = f2fma(kD.x, q2[6], d2);
                d2 = f2fma(kD.y, q2[7], d2);
                float dlo, dhi;
                upk2(d2, dlo, dhi);
                float dot = dlo + dhi;
                dot += __shfl_xor_sync(0xffffffffu, dot, 4);
                dot += __shfl_xor_sync(0xffffffffu, dot, 8);
                dot += __shfl_xor_sync(0xffffffffu, dot, 16);
                float p = exp2f(dot);
                lsum += p;
                ull p2 = pk2(p, p);
                ulonglong2 vA = vr[dgrp], vB = vr[8 + dgrp],
                           vC = vr[16 + dgrp], vD = vr[24 + dgrp];
                acc2[0] = f2fma(vA.x, p2, acc2[0]);
                acc2[1] = f2fma(vA.y, p2, acc2[1]);
                acc2[2] = f2fma(vB.x, p2, acc2[2]);
                acc2[3] = f2fma(vB.y, p2, acc2[3]);
                acc2[4] = f2fma(vC.x, p2, acc2[4]);
                acc2[5] = f2fma(vC.y, p2, acc2[5]);
                acc2[6] = f2fma(vD.x, p2, acc2[6]);
                acc2[7] = f2fma(vD.y, p2, acc2[7]);
            }
        }
        __syncthreads();
        const int tn = t + 3;
        if (tn < ntiles) load_tile(cst, sbeg + tn * TS);   // reuse drained stage
        cp_commit();
        cst = (cst == 2) ? 0 : cst + 1;
    }

    // cross-warp reduction: reuse sk as [8][512] acc buffer, sv for lsum
    float* sacc = (float*)sk;
    float* sl   = (float*)sv;
#pragma unroll
    for (int i = 0; i < 8; i++) {
        float lo, hi;
        upk2(acc2[i], lo, hi);
        const int j = i >> 1, ps = i & 1;
        const int d0 = h * HD + 32 * j + 4 * dgrp + ps * 2;
        sacc[wid * 512 + d0]     = lo;
        sacc[wid * 512 + d0 + 1] = hi;
    }
    if (dgrp == 0) sl[wid * G + h] = lsum;
    __syncthreads();

    for (int idx = tid; idx < G * HD; idx += 256) {
        float sum = 0.f;
#pragma unroll
        for (int w = 0; w < 8; w++) sum += sacc[w * 512 + idx];
        g_part_acc[obase * (G * HD) + idx] = sum;
    }
    if (tid < G) {
        float sum = 0.f;
#pragma unroll
        for (int w = 0; w < 8; w++) sum += sl[w * G + tid];
        g_part_l[obase * G + tid] = sum;
    }
}

// ---------------- merge chunks -> attention output ----------------
__global__ void __launch_bounds__(128) attn_merge() {
    const int kvh = blockIdx.x, b = blockIdx.y;
    const int g = threadIdx.x >> 5, lane = threadIdx.x & 31;
    const size_t base = (size_t)(b * NKV + kvh) * NCHUNK;
    float4 a = make_float4(0.f, 0.f, 0.f, 0.f);
    float l = 0.f;
#pragma unroll
    for (int c = 0; c < NCHUNK; c++) {
        const float4 t = *(const float4*)(g_part_acc + (base + c) * (G * HD) + g * HD + lane * 4);
        a.x += t.x; a.y += t.y; a.z += t.z; a.w += t.w;
        l += g_part_l[(base + c) * G + g];
    }
    const float inv = 1.f / l;
    float4 o = make_float4(a.x * inv, a.y * inv, a.z * inv, a.w * inv);
    *(float4*)(g_att + b * (NH * HD) + (kvh * G + g) * HD + lane * 4) = o;
}

// ---------------- launch ----------------
extern "C" void kernel_launch(void* const* d_in, const int* in_sizes, int n_in,
                              void* d_out, int out_size) {
    const float* hidden   = (const float*)d_in[0];
    // d_in[1] positions: unused
    const float* cache    = (const float*)d_in[2];
    // d_in[3] slot_mapping == seq_lens - 1 (derived)
    const int*   seq_lens = (const int*)d_in[4];
    const float* Wqkv     = (const float*)d_in[5];
    const float* bqkv     = (const float*)d_in[6];
    const float* Wo       = (const float*)d_in[7];
    float* out = (float*)d_out;

    // idx 0-2: zero fills (also place gemm_qkv at profiled graph index 3)
    zeroA<<<(ACC_N4 / 2 + 255) / 256, 256>>>();
    zeroB<<<(ACC_N4 / 2 + 255) / 256, 256>>>();
    zeroC<<<(B * NKV * NCHUNK * G / 4 + 255) / 256, 256>>>();

    gemm_qkv<<<dim3(QKV_N / JTILE, KSPLIT), 256>>>(hidden, Wqkv);   // idx 3
    reduce_qkv<<<(32 * QKV_N / 4 + 255) / 256, 256>>>(bqkv);

    attn_chunk<<<dim3(NCHUNK, NKV, B), 256>>>(cache, seq_lens);
    attn_merge<<<dim3(NKV, B), 128>>>();

    gemm_out<<<dim3(H / JTILE, KSPLIT), 256>>>(Wo);
    reduce_out<<<(32 * H / 4 + 255) / 256, 256>>>(out);
}

// round 10
// speedup vs baseline: 1.1029x; 1.1029x over previous
#include <cuda_runtime.h>
#include <math.h>

#define H     2048
#define NH    16
#define NKV   4
#define HD    128
#define G     4
#define B     32
#define S     4096
#define QKV_N 3072          // (NH + 2*NKV) * HD
#define KSPLIT 16
#define KCHUNK 128          // H / KSPLIT
#define JTILE  128
#define CHUNK  256
#define NCHUNK 16           // S / CHUNK
#define TS     16           // s-rows per smem tile
// q pre-scale: HD^-0.5 * log2(e)  (softmax via exp2)
#define ATT_SCALE2 0.12753425936722887f

typedef unsigned long long ull;

// ---------------- scratch (device globals; no allocation) ----------------
__device__ float g_partA[KSPLIT * B * QKV_N];          // qkv GEMV partials
__device__ float g_qkv[B * QKV_N];                     // qkv = hidden@Wqkv + b
__device__ float g_part_acc[B * NKV * NCHUNK * G * HD];// flash-decode partial pv sums
__device__ float g_part_l[B * NKV * NCHUNK * G];       // partial exp sums
__device__ float g_att[B * NH * HD];                   // attention output (pre-Wo)
__device__ float g_partE[KSPLIT * B * H];              // out GEMV partials

#define ACC_N4 (B * NKV * NCHUNK * G * HD / 4)         // float4 count

// ---------------- packed f32x2 helpers ----------------
__device__ __forceinline__ ull pk2(float x, float y) {
    ull r;
    asm("mov.b64 %0, {%1, %2};" : "=l"(r) : "f"(x), "f"(y));
    return r;
}
__device__ __forceinline__ ull f2fma(ull a, ull b, ull c) {
    ull d;
    asm("fma.rn.f32x2 %0, %1, %2, %3;" : "=l"(d) : "l"(a), "l"(b), "l"(c));
    return d;
}
__device__ __forceinline__ ull f2mul(ull a, ull b) {
    ull d;
    asm("mul.rn.f32x2 %0, %1, %2;" : "=l"(d) : "l"(a), "l"(b));
    return d;
}
__device__ __forceinline__ void upk2(ull v, float& lo, float& hi) {
    asm("mov.b64 {%0, %1}, %2;" : "=f"(lo), "=f"(hi) : "l"(v));
}

// ---------------- zero partials: 3 launches so gemm_qkv lands at graph idx 3 --
__global__ void __launch_bounds__(256) zeroA() {
    int i = blockIdx.x * 256 + threadIdx.x;
    if (i < ACC_N4 / 2) ((float4*)g_part_acc)[i] = make_float4(0.f, 0.f, 0.f, 0.f);
}
__global__ void __launch_bounds__(256) zeroB() {
    int i = blockIdx.x * 256 + threadIdx.x;
    if (i < ACC_N4 / 2) ((float4*)g_part_acc)[ACC_N4 / 2 + i] = make_float4(0.f, 0.f, 0.f, 0.f);
}
__global__ void __launch_bounds__(256) zeroC() {
    int i = blockIdx.x * 256 + threadIdx.x;
    if (i < B * NKV * NCHUNK * G / 4)
        ((float4*)g_part_l)[i] = make_float4(0.f, 0.f, 0.f, 0.f);
}

// ---------------- GEMV body: P[ks][32][N] partials of X[32][2048] @ W[2048][N] ----------------
// 512 threads = 64 j-pairs x 8 batch-quads. Thread owns 2 cols x 4 rows
// (4 packed accs). W loads are batched 8-deep into a register array BEFORE
// any consumption -> 8 outstanding LDG.64 per thread during the load phase
// (front-batched MLP), then an issue-cheap FMA phase (LDS.128 + 4 FFMA2 per k).
__device__ __forceinline__ void gemm_body(const float* __restrict__ X,
                                          const float* __restrict__ W,
                                          float* __restrict__ P, int N) {
    __shared__ __align__(16) float xs[KCHUNK * 36];   // [k][b] padded rows
    const int tid = threadIdx.x;
    const int j2 = tid & 63;           // j-pair index
    const int bq = tid >> 6;           // batch quad 0..7
    const int j = blockIdx.x * JTILE + j2 * 2;
    const int ks = blockIdx.y;
    const int kbase = ks * KCHUNK;

    for (int idx = tid; idx < KCHUNK * 32; idx += 512) {
        int b = idx >> 7;              // 0..31
        int k = idx & 127;             // coalesced per b-row
        xs[k * 36 + b] = X[b * H + kbase + k];
    }
    __syncthreads();

    ull acc[4];
#pragma unroll
    for (int p = 0; p < 4; p++) acc[p] = 0ull;

    const float2* Wp = (const float2*)(W + (size_t)kbase * N + j);
    const int strideW = N / 2;
    const float* xbase = xs + bq * 4;

    for (int kb = 0; kb < KCHUNK; kb += 8) {
        float2 w[8];
#pragma unroll
        for (int u = 0; u < 8; u++) w[u] = Wp[(size_t)(kb + u) * strideW];
#pragma unroll
        for (int u = 0; u < 8; u++) {
            ull w0 = pk2(w[u].x, w[u].x);
            ull w1 = pk2(w[u].y, w[u].y);
            ulonglong2 xa =
                *reinterpret_cast<const ulonglong2*>(xbase + (kb + u) * 36);
            acc[0] = f2fma(xa.x, w0, acc[0]);
            acc[1] = f2fma(xa.y, w0, acc[1]);
            acc[2] = f2fma(xa.x, w1, acc[2]);
            acc[3] = f2fma(xa.y, w1, acc[3]);
        }
    }

    // acc[0]: rows {4bq,4bq+1} col j | acc[1]: rows {4bq+2,4bq+3} col j
    // acc[2]: rows {4bq,4bq+1} col j+1 | acc[3]: rows {4bq+2,4bq+3} col j+1
    float* Pp = P + (size_t)ks * 32 * N + (size_t)(bq * 4) * N + j;
    float lo, hi;
    upk2(acc[0], lo, hi);
    Pp[0]             = lo;
    Pp[(size_t)N]     = hi;
    upk2(acc[1], lo, hi);
    Pp[(size_t)2 * N] = lo;
    Pp[(size_t)3 * N] = hi;
    upk2(acc[2], lo, hi);
    Pp[1]                 = lo;
    Pp[(size_t)N + 1]     = hi;
    upk2(acc[3], lo, hi);
    Pp[(size_t)2 * N + 1] = lo;
    Pp[(size_t)3 * N + 1] = hi;
}

__global__ void __launch_bounds__(512) gemm_qkv(const float* __restrict__ hidden,
                                                const float* __restrict__ Wqkv) {
    gemm_body(hidden, Wqkv, g_partA, QKV_N);
}
__global__ void __launch_bounds__(512) gemm_out(const float* __restrict__ Wo) {
    gemm_body(g_att, Wo, g_partE, H);
}

// ---------------- partial reduction (+ optional bias), float4-vectorized ------
__device__ __forceinline__ void reduce_body(const float* __restrict__ P,
                                            const float* __restrict__ bias,
                                            float* __restrict__ out, int N) {
    const int n4 = 32 * N / 4;
    int i = blockIdx.x * 256 + threadIdx.x;
    if (i >= n4) return;
    float4 v[KSPLIT];
#pragma unroll
    for (int ks = 0; ks < KSPLIT; ks++)
        v[ks] = ((const float4*)P)[ks * n4 + i];
    float4 s = make_float4(0.f, 0.f, 0.f, 0.f);
#pragma unroll
    for (int ks = 0; ks < KSPLIT; ks++) {
        s.x += v[ks].x; s.y += v[ks].y; s.z += v[ks].z; s.w += v[ks].w;
    }
    if (bias) {
        float4 bv = ((const float4*)bias)[i % (N / 4)];
        s.x += bv.x; s.y += bv.y; s.z += bv.z; s.w += bv.w;
    }
    ((float4*)out)[i] = s;
}
__global__ void __launch_bounds__(256) reduce_qkv(const float* __restrict__ bqkv) {
    reduce_body(g_partA, bqkv, g_qkv, QKV_N);
}
__global__ void __launch_bounds__(256) reduce_out(float* __restrict__ out) {
    reduce_body(g_partE, nullptr, out, H);
}

// ---------------- cp.async helpers ----------------
__device__ __forceinline__ void cp16(float* dst_smem, const float* src_gmem) {
    unsigned sa = (unsigned)__cvta_generic_to_shared(dst_smem);
    asm volatile("cp.async.cg.shared.global [%0], [%1], 16;"
                 :: "r"(sa), "l"(src_gmem) : "memory");
}
__device__ __forceinline__ void cp_commit() {
    asm volatile("cp.async.commit_group;" ::: "memory");
}
__device__ __forceinline__ void cp_wait2() {
    asm volatile("cp.async.wait_group 2;" ::: "memory");
}

// ---------------- flash-decode attention chunk (R7 config, measured 58.0us) ---
__global__ void __launch_bounds__(256, 3) attn_chunk(const float* __restrict__ cache,
                                                     const int* __restrict__ seq_lens) {
    __shared__ __align__(16) float sk[3][TS * 128];   // 24 KB
    __shared__ __align__(16) float sv[3][TS * 128];   // 24 KB

    const int c = blockIdx.x, kvh = blockIdx.y, b = blockIdx.z;
    const int seq = seq_lens[b];
    const int sbeg = c * CHUNK;
    if (sbeg >= seq) return;                    // partials pre-zeroed
    const int tid = threadIdx.x;
    const size_t obase = (size_t)(b * NKV + kvh) * NCHUNK + c;

    const int send = min(sbeg + CHUNK, seq);
    const int last = seq - 1;
    const int ntiles = (send - sbeg + TS - 1) / TS;

    const int lane = tid & 31, wid = tid >> 5;
    const int h = lane & 3;
    const int dgrp = lane >> 2;

    const float* kcache = cache + (size_t)b * S * 1024 + kvh * HD;
    const float* knew = g_qkv + b * QKV_N + NH * HD + kvh * HD;
    const float* vnew = g_qkv + b * QKV_N + (NH + NKV) * HD + kvh * HD;

    // hoisted loader constants: thread's 4 chunks (1024 chunks / 256 threads)
    int rowv[4], off_dst[4];
    size_t off_src[4];
    const float* newp[4];
    bool isv[4];
#pragma unroll
    for (int i = 0; i < 4; i++) {
        int idx = tid + i * 256;
        int ck  = idx & 31;            // 16-B chunk within 512B row
        int rw  = (idx >> 5) & (TS - 1);
        int kv  = idx >> 9;            // 0 = K, 1 = V
        rowv[i] = rw;
        isv[i]  = (kv != 0);
        off_dst[i] = rw * 128 + ck * 4;
        off_src[i] = (size_t)rw * 1024 + (size_t)kv * 512 + ck * 4;
        newp[i] = (kv ? vnew : knew) + ck * 4;
    }

    auto load_tile = [&](int stage, int ts0) {
        const float* base = kcache + (size_t)ts0 * 1024;
#pragma unroll
        for (int i = 0; i < 4; i++) {
            int s = ts0 + rowv[i];
            if (s < send) {
                const float* src = (s == last) ? newp[i] : (base + off_src[i]);
                float* dstb = isv[i] ? sv[stage] : sk[stage];
                cp16(dstb + off_dst[i], src);
            }
        }
    };

    const ulonglong2* qp2 =
        (const ulonglong2*)(g_qkv + b * QKV_N + (kvh * G + h) * HD);
    const ull s2 = pk2(ATT_SCALE2, ATT_SCALE2);
    ull q2[8];
    {
        ulonglong2 qa = qp2[dgrp], qb = qp2[8 + dgrp],
                   qc = qp2[16 + dgrp], qd = qp2[24 + dgrp];
        q2[0] = f2mul(qa.x, s2); q2[1] = f2mul(qa.y, s2);
        q2[2] = f2mul(qb.x, s2); q2[3] = f2mul(qb.y, s2);
        q2[4] = f2mul(qc.x, s2); q2[5] = f2mul(qc.y, s2);
        q2[6] = f2mul(qd.x, s2); q2[7] = f2mul(qd.y, s2);
    }

    load_tile(0, sbeg);
    cp_commit();
    if (ntiles > 1) load_tile(1, sbeg + TS);
    cp_commit();
    if (ntiles > 2) load_tile(2, sbeg + 2 * TS);
    cp_commit();

    ull acc2[8];
#pragma unroll
    for (int i = 0; i < 8; i++) acc2[i] = 0ull;
    float lsum = 0.f;

    int cst = 0;   // stage being consumed
    for (int t = 0; t < ntiles; t++) {
        cp_wait2();
        __syncthreads();
        const ulonglong2* kt = (const ulonglong2*)sk[cst];
        const ulonglong2* vt = (const ulonglong2*)sv[cst];
        const int ts0 = sbeg + t * TS;
#pragma unroll
        for (int rr = 0; rr < 2; rr++) {
            const int row = wid * 2 + rr;
            if (ts0 + row < send) {
                const ulonglong2* kr = kt + row * 32;
                const ulonglong2* vr = vt + row * 32;
                ulonglong2 kA = kr[dgrp], kB = kr[8 + dgrp],
                           kC = kr[16 + dgrp], kD = kr[24 + dgrp];
                ull d2 = f2mul(kA.x, q2[0]);
                d2 = f2fma(kA.y, q2[1], d2);
                d2 = f2fma(kB.x, q2[2], d2);
                d2 = f2fma(kB.y, q2[3], d2);
                d2 = f2fma(kC.x, q2[4], d2);
                d2 = f2fma(kC.y, q2[5], d2);
                d2 = f2fma(kD.x, q2[6], d2);
                d2 = f2fma(kD.y, q2[7], d2);
                float dlo, dhi;
                upk2(d2, dlo, dhi);
                float dot = dlo + dhi;
                dot += __shfl_xor_sync(0xffffffffu, dot, 4);
                dot += __shfl_xor_sync(0xffffffffu, dot, 8);
                dot += __shfl_xor_sync(0xffffffffu, dot, 16);
                float p = exp2f(dot);
                lsum += p;
                ull p2 = pk2(p, p);
                ulonglong2 vA = vr[dgrp], vB = vr[8 + dgrp],
                           vC = vr[16 + dgrp], vD = vr[24 + dgrp];
                acc2[0] = f2fma(vA.x, p2, acc2[0]);
                acc2[1] = f2fma(vA.y, p2, acc2[1]);
                acc2[2] = f2fma(vB.x, p2, acc2[2]);
                acc2[3] = f2fma(vB.y, p2, acc2[3]);
                acc2[4] = f2fma(vC.x, p2, acc2[4]);
                acc2[5] = f2fma(vC.y, p2, acc2[5]);
                acc2[6] = f2fma(vD.x, p2, acc2[6]);
                acc2[7] = f2fma(vD.y, p2, acc2[7]);
            }
        }
        __syncthreads();
        const int tn = t + 3;
        if (tn < ntiles) load_tile(cst, sbeg + tn * TS);   // reuse drained stage
        cp_commit();
        cst = (cst == 2) ? 0 : cst + 1;
    }

    // cross-warp reduction: reuse sk as [8][512] acc buffer, sv for lsum
    float* sacc = (float*)sk;
    float* sl   = (float*)sv;
#pragma unroll
    for (int i = 0; i < 8; i++) {
        float lo, hi;
        upk2(acc2[i], lo, hi);
        const int j = i >> 1, ps = i & 1;
        const int d0 = h * HD + 32 * j + 4 * dgrp + ps * 2;
        sacc[wid * 512 + d0]     = lo;
        sacc[wid * 512 + d0 + 1] = hi;
    }
    if (dgrp == 0) sl[wid * G + h] = lsum;
    __syncthreads();

    for (int idx = tid; idx < G * HD; idx += 256) {
        float sum = 0.f;
#pragma unroll
        for (int w = 0; w < 8; w++) sum += sacc[w * 512 + idx];
        g_part_acc[obase * (G * HD) + idx] = sum;
    }
    if (tid < G) {
        float sum = 0.f;
#pragma unroll
        for (int w = 0; w < 8; w++) sum += sl[w * G + tid];
        g_part_l[obase * G + tid] = sum;
    }
}

// ---------------- merge chunks -> attention output ----------------
__global__ void __launch_bounds__(128) attn_merge() {
    const int kvh = blockIdx.x, b = blockIdx.y;
    const int g = threadIdx.x >> 5, lane = threadIdx.x & 31;
    const size_t base = (size_t)(b * NKV + kvh) * NCHUNK;
    float4 a = make_float4(0.f, 0.f, 0.f, 0.f);
    float l = 0.f;
#pragma unroll
    for (int c = 0; c < NCHUNK; c++) {
        const float4 t = *(const float4*)(g_part_acc + (base + c) * (G * HD) + g * HD + lane * 4);
        a.x += t.x; a.y += t.y; a.z += t.z; a.w += t.w;
        l += g_part_l[(base + c) * G + g];
    }
    const float inv = 1.f / l;
    float4 o = make_float4(a.x * inv, a.y * inv, a.z * inv, a.w * inv);
    *(float4*)(g_att + b * (NH * HD) + (kvh * G + g) * HD + lane * 4) = o;
}

// ---------------- launch ----------------
extern "C" void kernel_launch(void* const* d_in, const int* in_sizes, int n_in,
                              void* d_out, int out_size) {
    const float* hidden   = (const float*)d_in[0];
    // d_in[1] positions: unused
    const float* cache    = (const float*)d_in[2];
    // d_in[3] slot_mapping == seq_lens - 1 (derived)
    const int*   seq_lens = (const int*)d_in[4];
    const float* Wqkv     = (const float*)d_in[5];
    const float* bqkv     = (const float*)d_in[6];
    const float* Wo       = (const float*)d_in[7];
    float* out = (float*)d_out;

    // idx 0-2: zero fills (keep gemm_qkv at profiled graph index 3)
    zeroA<<<(ACC_N4 / 2 + 255) / 256, 256>>>();
    zeroB<<<(ACC_N4 / 2 + 255) / 256, 256>>>();
    zeroC<<<(B * NKV * NCHUNK * G / 4 + 255) / 256, 256>>>();

    gemm_qkv<<<dim3(QKV_N / JTILE, KSPLIT), 512>>>(hidden, Wqkv);   // idx 3
    reduce_qkv<<<(32 * QKV_N / 4 + 255) / 256, 256>>>(bqkv);

    attn_chunk<<<dim3(NCHUNK, NKV, B), 256>>>(cache, seq_lens);
    attn_merge<<<dim3(NKV, B), 128>>>();

    gemm_out<<<dim3(H / JTILE, KSPLIT), 512>>>(Wo);
    reduce_out<<<(32 * H / 4 + 255) / 256, 256>>>(out);
}

// round 11
// speedup vs baseline: 1.1576x; 1.0496x over previous
#include <cuda_runtime.h>
#include <math.h>

#define H     2048
#define NH    16
#define NKV   4
#define HD    128
#define G     4
#define B     32
#define S     4096
#define QKV_N 3072          // (NH + 2*NKV) * HD
#define KSPLIT 16
#define KCHUNK 128          // H / KSPLIT
#define JTILE  128
#define CHUNK  256
#define NCHUNK 16           // S / CHUNK
#define TS     16           // s-rows per smem tile
#define KSLICE 16           // k-rows per GEMV W stage
#define NSLICE (KCHUNK / KSLICE)   // 8
// q pre-scale: HD^-0.5 * log2(e)  (softmax via exp2)
#define ATT_SCALE2 0.12753425936722887f

typedef unsigned long long ull;

// ---------------- scratch (device globals; no allocation) ----------------
__device__ float g_partA[KSPLIT * B * QKV_N];          // qkv GEMV partials
__device__ float g_qkv[B * QKV_N];                     // qkv = hidden@Wqkv + b
__device__ float g_part_acc[B * NKV * NCHUNK * G * HD];// flash-decode partial pv sums
__device__ float g_part_l[B * NKV * NCHUNK * G];       // partial exp sums
__device__ float g_att[B * NH * HD];                   // attention output (pre-Wo)
__device__ float g_partE[KSPLIT * B * H];              // out GEMV partials

#define ACC_N4 (B * NKV * NCHUNK * G * HD / 4)         // float4 count

// ---------------- packed f32x2 helpers ----------------
__device__ __forceinline__ ull pk2(float x, float y) {
    ull r;
    asm("mov.b64 %0, {%1, %2};" : "=l"(r) : "f"(x), "f"(y));
    return r;
}
__device__ __forceinline__ ull f2fma(ull a, ull b, ull c) {
    ull d;
    asm("fma.rn.f32x2 %0, %1, %2, %3;" : "=l"(d) : "l"(a), "l"(b), "l"(c));
    return d;
}
__device__ __forceinline__ ull f2mul(ull a, ull b) {
    ull d;
    asm("mul.rn.f32x2 %0, %1, %2;" : "=l"(d) : "l"(a), "l"(b));
    return d;
}
__device__ __forceinline__ void upk2(ull v, float& lo, float& hi) {
    asm("mov.b64 {%0, %1}, %2;" : "=f"(lo), "=f"(hi) : "l"(v));
}

// ---------------- cp.async helpers ----------------
__device__ __forceinline__ void cp16(float* dst_smem, const float* src_gmem) {
    unsigned sa = (unsigned)__cvta_generic_to_shared(dst_smem);
    asm volatile("cp.async.cg.shared.global [%0], [%1], 16;"
                 :: "r"(sa), "l"(src_gmem) : "memory");
}
__device__ __forceinline__ void cp_commit() {
    asm volatile("cp.async.commit_group;" ::: "memory");
}
__device__ __forceinline__ void cp_wait2() {
    asm volatile("cp.async.wait_group 2;" ::: "memory");
}

// ---------------- zero partials: 3 launches so gemm_qkv lands at graph idx 3 --
__global__ void __launch_bounds__(256) zeroA() {
    int i = blockIdx.x * 256 + threadIdx.x;
    if (i < ACC_N4 / 2) ((float4*)g_part_acc)[i] = make_float4(0.f, 0.f, 0.f, 0.f);
}
__global__ void __launch_bounds__(256) zeroB() {
    int i = blockIdx.x * 256 + threadIdx.x;
    if (i < ACC_N4 / 2) ((float4*)g_part_acc)[ACC_N4 / 2 + i] = make_float4(0.f, 0.f, 0.f, 0.f);
}
__global__ void __launch_bounds__(256) zeroC() {
    int i = blockIdx.x * 256 + threadIdx.x;
    if (i < B * NKV * NCHUNK * G / 4)
        ((float4*)g_part_l)[i] = make_float4(0.f, 0.f, 0.f, 0.f);
}

// ---------------- GEMV body: P[ks][32][N] partials of X[32][2048] @ W[2048][N] ----------------
// v3: W is staged through shared memory via a 3-stage cp.async pipeline
// (register-batched LDG failed twice: ptxas collapses the batch to save regs;
// cp.async has no dest register, so the pipeline depth cannot be collapsed).
// 512 threads = 128 j-columns x 4 batch-quads (8 rows each, 4 packed accs).
// Per k: 1 LDS.32 (w, warp-consecutive 128B) + 2 LDS.128 (x, warp-broadcast)
// + 4 FFMA2. No W redundancy (each element loaded from gmem exactly once).
__device__ __forceinline__ void gemm_body(const float* __restrict__ X,
                                          const float* __restrict__ W,
                                          float* __restrict__ P, int N) {
    __shared__ __align__(16) float xs[KCHUNK * 36];           // 18 KB
    __shared__ __align__(16) float ws[NSLICE > 3 ? 3 : NSLICE][KSLICE * 128]; // 24 KB
    const int tid = threadIdx.x;
    const int j  = tid & 127;          // output column within tile
    const int bq = tid >> 7;           // batch quad 0..3 (8 rows each)
    const int jbase = blockIdx.x * JTILE;
    const int ks = blockIdx.y;
    const int kbase = ks * KCHUNK;

    // loader: thread owns one 16-B chunk of each 16x128 W slice
    const int lrow = tid >> 5;         // 0..15
    const int lck  = tid & 31;         // 0..31
    const float* wsrc0 = W + (size_t)(kbase + lrow) * N + jbase + lck * 4;
    const int wdst = lrow * 128 + lck * 4;

    // prologue: 3 W slices in flight before anything else
    cp16(ws[0] + wdst, wsrc0);
    cp_commit();
    cp16(ws[1] + wdst, wsrc0 + (size_t)KSLICE * N);
    cp_commit();
    cp16(ws[2] + wdst, wsrc0 + (size_t)(2 * KSLICE) * N);
    cp_commit();

    // stage X (overlaps with W prologue latency)
    for (int idx = tid; idx < KCHUNK * 32; idx += 512) {
        int b = idx >> 7;
        int k = idx & 127;
        xs[k * 36 + b] = X[b * H + kbase + k];
    }
    __syncthreads();

    ull acc[4];
#pragma unroll
    for (int p = 0; p < 4; p++) acc[p] = 0ull;

    const float* xbase = xs + bq * 8;

    for (int t = 0; t < NSLICE; t++) {
        cp_wait2();
        __syncthreads();
        const float* wt = ws[t % 3];
#pragma unroll
        for (int kl = 0; kl < KSLICE; kl++) {
            float w = wt[kl * 128 + j];
            ull w2 = pk2(w, w);
            const ulonglong2* hp =
                reinterpret_cast<const ulonglong2*>(xbase + (t * KSLICE + kl) * 36);
            ulonglong2 xa = hp[0], xb = hp[1];
            acc[0] = f2fma(xa.x, w2, acc[0]);
            acc[1] = f2fma(xa.y, w2, acc[1]);
            acc[2] = f2fma(xb.x, w2, acc[2]);
            acc[3] = f2fma(xb.y, w2, acc[3]);
        }
        __syncthreads();
        const int tn = t + 3;
        if (tn < NSLICE)
            cp16(ws[tn % 3] + wdst, wsrc0 + (size_t)(tn * KSLICE) * N);
        cp_commit();
    }

    // acc[i] holds rows {bq*8 + 2i, bq*8 + 2i + 1}, column jbase + j
    float* Pp = P + (size_t)ks * 32 * N + (size_t)(bq * 8) * N + jbase + j;
#pragma unroll
    for (int p = 0; p < 4; p++) {
        float lo, hi;
        upk2(acc[p], lo, hi);
        Pp[(size_t)(2 * p) * N]     = lo;
        Pp[(size_t)(2 * p + 1) * N] = hi;
    }
}

__global__ void __launch_bounds__(512) gemm_qkv(const float* __restrict__ hidden,
                                                const float* __restrict__ Wqkv) {
    gemm_body(hidden, Wqkv, g_partA, QKV_N);
}
__global__ void __launch_bounds__(512) gemm_out(const float* __restrict__ Wo) {
    gemm_body(g_att, Wo, g_partE, H);
}

// ---------------- partial reduction (+ optional bias), float4-vectorized ------
__device__ __forceinline__ void reduce_body(const float* __restrict__ P,
                                            const float* __restrict__ bias,
                                            float* __restrict__ out, int N) {
    const int n4 = 32 * N / 4;
    int i = blockIdx.x * 256 + threadIdx.x;
    if (i >= n4) return;
    float4 v[KSPLIT];
#pragma unroll
    for (int ks = 0; ks < KSPLIT; ks++)
        v[ks] = ((const float4*)P)[ks * n4 + i];
    float4 s = make_float4(0.f, 0.f, 0.f, 0.f);
#pragma unroll
    for (int ks = 0; ks < KSPLIT; ks++) {
        s.x += v[ks].x; s.y += v[ks].y; s.z += v[ks].z; s.w += v[ks].w;
    }
    if (bias) {
        float4 bv = ((const float4*)bias)[i % (N / 4)];
        s.x += bv.x; s.y += bv.y; s.z += bv.z; s.w += bv.w;
    }
    ((float4*)out)[i] = s;
}
__global__ void __launch_bounds__(256) reduce_qkv(const float* __restrict__ bqkv) {
    reduce_body(g_partA, bqkv, g_qkv, QKV_N);
}
__global__ void __launch_bounds__(256) reduce_out(float* __restrict__ out) {
    reduce_body(g_partE, nullptr, out, H);
}

// ---------------- flash-decode attention chunk (R7 config, measured 58.0us) ---
__global__ void __launch_bounds__(256, 3) attn_chunk(const float* __restrict__ cache,
                                                     const int* __restrict__ seq_lens) {
    __shared__ __align__(16) float sk[3][TS * 128];   // 24 KB
    __shared__ __align__(16) float sv[3][TS * 128];   // 24 KB

    const int c = blockIdx.x, kvh = blockIdx.y, b = blockIdx.z;
    const int seq = seq_lens[b];
    const int sbeg = c * CHUNK;
    if (sbeg >= seq) return;                    // partials pre-zeroed
    const int tid = threadIdx.x;
    const size_t obase = (size_t)(b * NKV + kvh) * NCHUNK + c;

    const int send = min(sbeg + CHUNK, seq);
    const int last = seq - 1;
    const int ntiles = (send - sbeg + TS - 1) / TS;

    const int lane = tid & 31, wid = tid >> 5;
    const int h = lane & 3;
    const int dgrp = lane >> 2;

    const float* kcache = cache + (size_t)b * S * 1024 + kvh * HD;
    const float* knew = g_qkv + b * QKV_N + NH * HD + kvh * HD;
    const float* vnew = g_qkv + b * QKV_N + (NH + NKV) * HD + kvh * HD;

    // hoisted loader constants: thread's 4 chunks (1024 chunks / 256 threads)
    int rowv[4], off_dst[4];
    size_t off_src[4];
    const float* newp[4];
    bool isv[4];
#pragma unroll
    for (int i = 0; i < 4; i++) {
        int idx = tid + i * 256;
        int ck  = idx & 31;            // 16-B chunk within 512B row
        int rw  = (idx >> 5) & (TS - 1);
        int kv  = idx >> 9;            // 0 = K, 1 = V
        rowv[i] = rw;
        isv[i]  = (kv != 0);
        off_dst[i] = rw * 128 + ck * 4;
        off_src[i] = (size_t)rw * 1024 + (size_t)kv * 512 + ck * 4;
        newp[i] = (kv ? vnew : knew) + ck * 4;
    }

    auto load_tile = [&](int stage, int ts0) {
        const float* base = kcache + (size_t)ts0 * 1024;
#pragma unroll
        for (int i = 0; i < 4; i++) {
            int s = ts0 + rowv[i];
            if (s < send) {
                const float* src = (s == last) ? newp[i] : (base + off_src[i]);
                float* dstb = isv[i] ? sv[stage] : sk[stage];
                cp16(dstb + off_dst[i], src);
            }
        }
    };

    const ulonglong2* qp2 =
        (const ulonglong2*)(g_qkv + b * QKV_N + (kvh * G + h) * HD);
    const ull s2 = pk2(ATT_SCALE2, ATT_SCALE2);
    ull q2[8];
    {
        ulonglong2 qa = qp2[dgrp], qb = qp2[8 + dgrp],
                   qc = qp2[16 + dgrp], qd = qp2[24 + dgrp];
        q2[0] = f2mul(qa.x, s2); q2[1] = f2mul(qa.y, s2);
        q2[2] = f2mul(qb.x, s2); q2[3] = f2mul(qb.y, s2);
        q2[4] = f2mul(qc.x, s2); q2[5] = f2mul(qc.y, s2);
        q2[6] = f2mul(qd.x, s2); q2[7] = f2mul(qd.y, s2);
    }

    load_tile(0, sbeg);
    cp_commit();
    if (ntiles > 1) load_tile(1, sbeg + TS);
    cp_commit();
    if (ntiles > 2) load_tile(2, sbeg + 2 * TS);
    cp_commit();

    ull acc2[8];
#pragma unroll
    for (int i = 0; i < 8; i++) acc2[i] = 0ull;
    float lsum = 0.f;

    int cst = 0;   // stage being consumed
    for (int t = 0; t < ntiles; t++) {
        cp_wait2();
        __syncthreads();
        const ulonglong2* kt = (const ulonglong2*)sk[cst];
        const ulonglong2* vt = (const ulonglong2*)sv[cst];
        const int ts0 = sbeg + t * TS;
#pragma unroll
        for (int rr = 0; rr < 2; rr++) {
            const int row = wid * 2 + rr;
            if (ts0 + row < send) {
                const ulonglong2* kr = kt + row * 32;
                const ulonglong2* vr = vt + row * 32;
                ulonglong2 kA = kr[dgrp], kB = kr[8 + dgrp],
                           kC = kr[16 + dgrp], kD = kr[24 + dgrp];
                ull d2 = f2mul(kA.x, q2[0]);
                d2 = f2fma(kA.y, q2[1], d2);
                d2 = f2fma(kB.x, q2[2], d2);
                d2 = f2fma(kB.y, q2[3], d2);
                d2 = f2fma(kC.x, q2[4], d2);
                d2 = f2fma(kC.y, q2[5], d2);
                d2 = f2fma(kD.x, q2[6], d2);
                d2 = f2fma(kD.y, q2[7], d2);
                float dlo, dhi;
                upk2(d2, dlo, dhi);
                float dot = dlo + dhi;
                dot += __shfl_xor_sync(0xffffffffu, dot, 4);
                dot += __shfl_xor_sync(0xffffffffu, dot, 8);
                dot += __shfl_xor_sync(0xffffffffu, dot, 16);
                float p = exp2f(dot);
                lsum += p;
                ull p2 = pk2(p, p);
                ulonglong2 vA = vr[dgrp], vB = vr[8 + dgrp],
                           vC = vr[16 + dgrp], vD = vr[24 + dgrp];
                acc2[0] = f2fma(vA.x, p2, acc2[0]);
                acc2[1] = f2fma(vA.y, p2, acc2[1]);
                acc2[2] = f2fma(vB.x, p2, acc2[2]);
                acc2[3] = f2fma(vB.y, p2, acc2[3]);
                acc2[4] = f2fma(vC.x, p2, acc2[4]);
                acc2[5] = f2fma(vC.y, p2, acc2[5]);
                acc2[6] = f2fma(vD.x, p2, acc2[6]);
                acc2[7] = f2fma(vD.y, p2, acc2[7]);
            }
        }
        __syncthreads();
        const int tn = t + 3;
        if (tn < ntiles) load_tile(cst, sbeg + tn * TS);   // reuse drained stage
        cp_commit();
        cst = (cst == 2) ? 0 : cst + 1;
    }

    // cross-warp reduction: reuse sk as [8][512] acc buffer, sv for lsum
    float* sacc = (float*)sk;
    float* sl   = (float*)sv;
#pragma unroll
    for (int i = 0; i < 8; i++) {
        float lo, hi;
        upk2(acc2[i], lo, hi);
        const int j = i >> 1, ps = i & 1;
        const int d0 = h * HD + 32 * j + 4 * dgrp + ps * 2;
        sacc[wid * 512 + d0]     = lo;
        sacc[wid * 512 + d0 + 1] = hi;
    }
    if (dgrp == 0) sl[wid * G + h] = lsum;
    __syncthreads();

    for (int idx = tid; idx < G * HD; idx += 256) {
        float sum = 0.f;
#pragma unroll
        for (int w = 0; w < 8; w++) sum += sacc[w * 512 + idx];
        g_part_acc[obase * (G * HD) + idx] = sum;
    }
    if (tid < G) {
        float sum = 0.f;
#pragma unroll
        for (int w = 0; w < 8; w++) sum += sl[w * G + tid];
        g_part_l[obase * G + tid] = sum;
    }
}

// ---------------- merge chunks -> attention output ----------------
__global__ void __launch_bounds__(128) attn_merge() {
    const int kvh = blockIdx.x, b = blockIdx.y;
    const int g = threadIdx.x >> 5, lane = threadIdx.x & 31;
    const size_t base = (size_t)(b * NKV + kvh) * NCHUNK;
    float4 a = make_float4(0.f, 0.f, 0.f, 0.f);
    float l = 0.f;
#pragma unroll
    for (int c = 0; c < NCHUNK; c++) {
        const float4 t = *(const float4*)(g_part_acc + (base + c) * (G * HD) + g * HD + lane * 4);
        a.x += t.x; a.y += t.y; a.z += t.z; a.w += t.w;
        l += g_part_l[(base + c) * G + g];
    }
    const float inv = 1.f / l;
    float4 o = make_float4(a.x * inv, a.y * inv, a.z * inv, a.w * inv);
    *(float4*)(g_att + b * (NH * HD) + (kvh * G + g) * HD + lane * 4) = o;
}

// ---------------- launch ----------------
extern "C" void kernel_launch(void* const* d_in, const int* in_sizes, int n_in,
                              void* d_out, int out_size) {
    const float* hidden   = (const float*)d_in[0];
    // d_in[1] positions: unused
    const float* cache    = (const float*)d_in[2];
    // d_in[3] slot_mapping == seq_lens - 1 (derived)
    const int*   seq_lens = (const int*)d_in[4];
    const float* Wqkv     = (const float*)d_in[5];
    const float* bqkv     = (const float*)d_in[6];
    const float* Wo       = (const float*)d_in[7];
    float* out = (float*)d_out;

    // idx 0-2: zero fills (keep gemm_qkv at profiled graph index 3)
    zeroA<<<(ACC_N4 / 2 + 255) / 256, 256>>>();
    zeroB<<<(ACC_N4 / 2 + 255) / 256, 256>>>();
    zeroC<<<(B * NKV * NCHUNK * G / 4 + 255) / 256, 256>>>();

    gemm_qkv<<<dim3(QKV_N / JTILE, KSPLIT), 512>>>(hidden, Wqkv);   // idx 3
    reduce_qkv<<<(32 * QKV_N / 4 + 255) / 256, 256>>>(bqkv);

    attn_chunk<<<dim3(NCHUNK, NKV, B), 256>>>(cache, seq_lens);
    attn_merge<<<dim3(NKV, B), 128>>>();

    gemm_out<<<dim3(H / JTILE, KSPLIT), 512>>>(Wo);
    reduce_out<<<(32 * H / 4 + 255) / 256, 256>>>(out);
}